// round 2
// baseline (speedup 1.0000x reference)
#include <cuda_runtime.h>

// GatedCNNLayer: X (16,4096,1024) f32, G (1024,2) f32, Gb (2,) f32
// out[b,p,:] = X[b,2p,:]*g0 + X[b,2p+2,:]*g1,
//   g = softmax(X[b,2p+1,:] @ G + Gb), p in [0,2047)
//
// Pair-chained streaming kernel: each block handles NP=8 consecutive pairs of
// one batch row-strip. The 'right' row of pair i is register-reused as the
// 'left' row of pair i+1 (cuts L1/L2 read requests ~25%). Software-pipelined
// with one __syncthreads per pair via double-buffered warp partials.

#define BATCH 16
#define SEQ   4096
#define DIM   1024
#define D4    (DIM / 4)      // 256 float4 per row
#define PAIRS 2047
#define NP    8              // pairs per block
#define NBLK  ((PAIRS + NP - 1) / NP)   // 256

__global__ __launch_bounds__(256, 8)
void gated_cnn_chain_kernel(const float* __restrict__ X,
                            const float* __restrict__ G,
                            const float* __restrict__ Gb,
                            float* __restrict__ out)
{
    const int b  = blockIdx.y;
    const int p0 = blockIdx.x * NP;
    const int t  = threadIdx.x;          // 0..255 -> 4 columns each
    const int warp = t >> 5, lane = t & 31;

    const int np = min(NP, PAIRS - p0);  // 8, or 7 for the last block

    const float4* __restrict__ X4 = (const float4*)X;
    const float4* __restrict__ G4 = (const float4*)G;
    float4* __restrict__ O4 = (float4*)out;

    // Hoisted gate weights for this thread's 8 columns (G is (d,2) interleaved)
    const float4 ga = G4[2 * t];       // {G[8t][0],G[8t][1],G[8t+1][0],G[8t+1][1]}
    const float4 gc = G4[2 * t + 1];
    const float gb0 = Gb[0], gb1 = Gb[1];

    __shared__ float sh[2][2][8];      // [buf][logit][warp]

    // row index (in float4 units) helpers
    const size_t rowbase = (size_t)b * SEQ;       // rows
    #define ROW4(r) (((rowbase + (size_t)(r)) * D4) + t)

    // Prologue: load left, mid, right for pair p0 (3 batched LDG.128)
    float4 L = X4[ROW4(2 * p0)];
    float4 M = X4[ROW4(2 * p0 + 1)];
    float4 R = X4[ROW4(2 * p0 + 2)];

    for (int i = 0; i < np; i++) {
        // Prefetch next pair's mid/right before the reduction barrier
        float4 Mn, Rn;
        if (i + 1 < np) {
            Mn = X4[ROW4(2 * (p0 + i + 1) + 1)];
            Rn = X4[ROW4(2 * (p0 + i + 1) + 2)];
        }

        // Gate logits for this thread's 4 columns of the mid row
        float s0 = M.x * ga.x + M.y * ga.z + M.z * gc.x + M.w * gc.z;
        float s1 = M.x * ga.y + M.y * ga.w + M.z * gc.y + M.w * gc.w;

        #pragma unroll
        for (int off = 16; off > 0; off >>= 1) {
            s0 += __shfl_xor_sync(0xFFFFFFFFu, s0, off);
            s1 += __shfl_xor_sync(0xFFFFFFFFu, s1, off);
        }
        const int buf = i & 1;
        if (lane == 0) { sh[buf][0][warp] = s0; sh[buf][1][warp] = s1; }
        __syncthreads();

        // Every thread sums the 8 warp partials (broadcast LDS) -> no 2nd barrier
        float a = gb0, c = gb1;
        #pragma unroll
        for (int j = 0; j < 8; j++) { a += sh[buf][0][j]; c += sh[buf][1][j]; }
        const float g0 = 1.0f / (1.0f + __expf(c - a));   // softmax over 2 logits
        const float g1 = 1.0f - g0;

        float4 o;
        o.x = L.x * g0 + R.x * g1;
        o.y = L.y * g0 + R.y * g1;
        o.z = L.z * g0 + R.z * g1;
        o.w = L.w * g0 + R.w * g1;
        O4[((size_t)b * PAIRS + (p0 + i)) * D4 + t] = o;

        // Chain: right row becomes next pair's left row (no reload)
        L = R; M = Mn; R = Rn;
    }
    #undef ROW4
}

extern "C" void kernel_launch(void* const* d_in, const int* in_sizes, int n_in,
                              void* d_out, int out_size)
{
    const float* X  = (const float*)d_in[0];
    const float* G  = (const float*)d_in[1];
    const float* Gb = (const float*)d_in[2];
    float* out = (float*)d_out;

    dim3 grid(NBLK, BATCH);
    gated_cnn_chain_kernel<<<grid, 256>>>(X, G, Gb, out);
}

// round 3
// speedup vs baseline: 1.0806x; 1.0806x over previous
#include <cuda_runtime.h>

// GatedCNNLayer: X (16,4096,1024) f32, G (1024,2) f32, Gb (2,) f32
// out[b,p,:] = X[b,2p,:]*g0 + X[b,2p+2,:]*g1,
//   g = softmax(X[b,2p+1,:] @ G + Gb), p in [0,2047)
//
// Warp-per-pair, barrier-free steady state. Each warp owns one (b,p):
// 32 lanes x 8 float4 = 1024 columns. All 24 LDG.128 (mid+left+right) are
// front-batched for max MLP; gate reduce is warp-shuffle-only. G is staged
// to smem once per block. __ldcs on read-once mids, __stcs on the output
// stream to keep L2 free for the even-row (left/right) reuse.

#define BATCH 16
#define SEQ   4096
#define DIM   1024
#define D4    (DIM / 4)      // 256 float4 per row
#define PAIRS 2047
#define WPB   8              // warps per block
#define NBLKX ((PAIRS + WPB - 1) / WPB)   // 256

__global__ __launch_bounds__(256)
void gated_cnn_warp_kernel(const float* __restrict__ X,
                           const float* __restrict__ G,
                           const float* __restrict__ Gb,
                           float* __restrict__ out)
{
    __shared__ float4 Gsh[2 * D4];   // 8 KB, interleaved (d,2) as float4 pairs

    const int t    = threadIdx.x;
    const int warp = t >> 5;
    const int lane = t & 31;

    // Stage G once per block (cold path, single barrier)
    {
        const float4* __restrict__ G4 = (const float4*)G;
        Gsh[t]       = G4[t];
        Gsh[t + 256] = G4[t + 256];
    }
    __syncthreads();

    const int p = blockIdx.x * WPB + warp;
    if (p >= PAIRS) return;
    const int b = blockIdx.y;

    const float4* __restrict__ X4 = (const float4*)X;
    float4* __restrict__ O4 = (float4*)out;

    const size_t rowL = ((size_t)b * SEQ + (size_t)(2 * p)) * D4;   // left row (f4 units)
    const size_t rowM = rowL + D4;
    const size_t rowR = rowM + D4;

    // ---- front-batched loads: 8 mid + 8 left + 8 right LDG.128 ----
    float4 M[8], L[8], R[8];
    #pragma unroll
    for (int j = 0; j < 8; j++) M[j] = __ldcs(&X4[rowM + j * 32 + lane]);
    #pragma unroll
    for (int j = 0; j < 8; j++) L[j] = X4[rowL + j * 32 + lane];
    #pragma unroll
    for (int j = 0; j < 8; j++) R[j] = X4[rowR + j * 32 + lane];

    // ---- gate logits from mids (smem-resident G) ----
    float s0 = 0.f, s1 = 0.f;
    #pragma unroll
    for (int j = 0; j < 8; j++) {
        const int idx = j * 32 + lane;
        const float4 m  = M[j];
        const float4 ga = Gsh[2 * idx];
        const float4 gc = Gsh[2 * idx + 1];
        s0 += m.x * ga.x + m.y * ga.z + m.z * gc.x + m.w * gc.z;
        s1 += m.x * ga.y + m.y * ga.w + m.z * gc.y + m.w * gc.w;
    }

    // ---- warp-only reduction (no block barrier) ----
    #pragma unroll
    for (int off = 16; off > 0; off >>= 1) {
        s0 += __shfl_xor_sync(0xFFFFFFFFu, s0, off);
        s1 += __shfl_xor_sync(0xFFFFFFFFu, s1, off);
    }
    s0 += __ldg(&Gb[0]);
    s1 += __ldg(&Gb[1]);

    // softmax over 2 logits: overflow-safe sigmoid form
    const float g0 = 1.0f / (1.0f + __expf(s1 - s0));
    const float g1 = 1.0f - g0;

    // ---- blend + streaming stores ----
    const size_t rowO = ((size_t)b * PAIRS + (size_t)p) * D4;
    #pragma unroll
    for (int j = 0; j < 8; j++) {
        float4 o;
        o.x = L[j].x * g0 + R[j].x * g1;
        o.y = L[j].y * g0 + R[j].y * g1;
        o.z = L[j].z * g0 + R[j].z * g1;
        o.w = L[j].w * g0 + R[j].w * g1;
        __stcs(&O4[rowO + j * 32 + lane], o);
    }
}

extern "C" void kernel_launch(void* const* d_in, const int* in_sizes, int n_in,
                              void* d_out, int out_size)
{
    const float* X  = (const float*)d_in[0];
    const float* G  = (const float*)d_in[1];
    const float* Gb = (const float*)d_in[2];
    float* out = (float*)d_out;

    dim3 grid(NBLKX, BATCH);
    gated_cnn_warp_kernel<<<grid, 256>>>(X, G, Gb, out);
}